// round 10
// baseline (speedup 1.0000x reference)
#include <cuda_runtime.h>
#include <math.h>

// Branchless prob-space q_posterior (K=2):
//  alpha = exp(la[t]); oma = exp(l1a[t]) = 1-alpha
//  Qh = alpha + oma/2 (x_t one-hot "hit"), Ql = 1e-30*alpha + oma/2 ("miss")
//  t>0 : ab = exp(lab[t-1]), c = 0.5*exp(l1ab[t-1])
//  t==0: ab = 1, c = 0   (then f0=e0, f1=1-e0 -> posterior = renorm(x0*Q), exact)
//  w0 = (ab*e0+c)*Q0 ; w1 = (ab*(1-e0)+c)*Q1 ; out = log(w/(w0+w1))
// Only class-0 of xt (one-hot) and x0 (log_softmax, K=2) are read: 268 MB total.

__global__ void __launch_bounds__(256) qpost_kernel(const float* __restrict__ xt,
                                                    const float* __restrict__ x0,
                                                    float* __restrict__ out,
                                                    const int* __restrict__ t_raw,
                                                    const float* __restrict__ la,
                                                    const float* __restrict__ l1a,
                                                    const float* __restrict__ lab,
                                                    const float* __restrict__ l1ab) {
    unsigned tid = blockIdx.x * 256u + threadIdx.x;
    size_t e = (size_t)tid << 4;                   // 16 spatial elems per thread
    unsigned b = (unsigned)(e >> 20);              // batch (uniform per thread tile)
    size_t base = ((size_t)b << 21) + (e & (((size_t)1 << 20) - 1));
    const size_t cstr = (size_t)1 << 20;           // class stride

    // ---- lane-0 scalar param loads (only 1/32 threads touch the L1tex queue) ----
    float vla = 0.f, vl1a = 0.f, vlab = 0.f, vl1ab = 0.f;
    int t = 0;
    if ((threadIdx.x & 31) == 0) {
        // int64-vs-int32 sniff (t in [0,1000); int64 LE high words are 0)
        int hw = t_raw[1] | t_raw[3] | t_raw[5] | t_raw[7];
        t = (hw == 0) ? t_raw[2 * b] : t_raw[b];
        vla  = la[t];
        vl1a = l1a[t];
        int tm = (t > 0) ? (t - 1) : 0;
        vlab  = lab[tm];
        vl1ab = l1ab[tm];
    }

    // ---- 8 front-batched streaming loads (MLP=8, independent of params) ----
    float4 xq0 = __ldcs((const float4*)(xt + base));
    float4 xq1 = __ldcs((const float4*)(xt + base + 4));
    float4 xq2 = __ldcs((const float4*)(xt + base + 8));
    float4 xq3 = __ldcs((const float4*)(xt + base + 12));
    float4 pq0 = __ldcs((const float4*)(x0 + base));
    float4 pq1 = __ldcs((const float4*)(x0 + base + 4));
    float4 pq2 = __ldcs((const float4*)(x0 + base + 8));
    float4 pq3 = __ldcs((const float4*)(x0 + base + 12));

    // ---- finish params on lane 0, broadcast (overlaps load latency) ----
    float Qh = 0.f, Ql = 0.f, ab = 0.f, c = 0.f;
    if ((threadIdx.x & 31) == 0) {
        float alpha = __expf(vla);
        float oma   = __expf(vl1a);                // 1 - alpha (+1e-40)
        Qh = fmaf(0.5f, oma, alpha);
        Ql = fmaf(0.5f, oma, 1e-30f * alpha);
        if (t == 0) { ab = 1.0f; c = 0.0f; }       // unifies the t==0 case exactly
        else        { ab = __expf(vlab); c = 0.5f * __expf(vl1ab); }
    }
    Qh = __shfl_sync(0xFFFFFFFFu, Qh, 0);
    Ql = __shfl_sync(0xFFFFFFFFu, Ql, 0);
    ab = __shfl_sync(0xFFFFFFFFu, ab, 0);
    c  = __shfl_sync(0xFFFFFFFFu, c,  0);
    float abc = ab + c;

    #pragma unroll
    for (int q = 0; q < 4; q++) {
        float4 xq = (q == 0) ? xq0 : (q == 1) ? xq1 : (q == 2) ? xq2 : xq3;
        float4 pq = (q == 0) ? pq0 : (q == 1) ? pq1 : (q == 2) ? pq2 : pq3;
        float4 o0, o1;
        #pragma unroll
        for (int k = 0; k < 4; k++) {
            float e0 = __expf(((const float*)&pq)[k]);   // exp(x01) = 1-e0 (K=2)
            float f0 = fmaf(ab, e0, c);
            float f1 = fmaf(-ab, e0, abc);               // ab*(1-e0)+c
            bool hi = (((const float*)&xq)[k] > -1.0f);  // one-hot hit on class 0?
            float w0 = f0 * (hi ? Qh : Ql);
            float w1 = f1 * (hi ? Ql : Qh);
            float r = __fdividef(1.0f, w0 + w1);
            ((float*)&o0)[k] = __logf(w0 * r);
            ((float*)&o1)[k] = __logf(w1 * r);
        }
        __stcs((float4*)(out + base + 4 * q),        o0);
        __stcs((float4*)(out + base + cstr + 4 * q), o1);
    }
}

extern "C" void kernel_launch(void* const* d_in, const int* in_sizes, int n_in,
                              void* d_out, int out_size) {
    const float* log_x_t = (const float*)d_in[0];
    const float* log_x_0 = (const float*)d_in[1];
    const float* la      = (const float*)d_in[2];
    const float* l1a     = (const float*)d_in[3];
    const float* lab     = (const float*)d_in[4];
    const float* l1ab    = (const float*)d_in[5];
    const int*   t_raw   = (const int*)d_in[6];

    // 16 * 2^20 spatial / 16 per thread = 1,048,576 threads = 4096 blocks
    qpost_kernel<<<4096, 256>>>(log_x_t, log_x_0, (float*)d_out,
                                t_raw, la, l1a, lab, l1ab);
}

// round 11
// speedup vs baseline: 1.2083x; 1.2083x over previous
#include <cuda_runtime.h>
#include <math.h>

// Branchless prob-space q_posterior (K=2), 268 MB total traffic:
//  alpha = exp(la[t]); oma = exp(l1a[t]) = 1-alpha
//  Qh = alpha + oma/2 (x_t one-hot "hit"), Ql = 1e-30*alpha + oma/2 ("miss")
//  t>0 : ab = exp(lab[t-1]), c = 0.5*exp(l1ab[t-1])
//  t==0: ab = 1, c = 0   (f0=e0, f1=1-e0 -> posterior = renorm(x0*Q): exact)
//  w0 = (ab*e0+c)*Q0 ; w1 = (ab*(1-e0)+c)*Q1 ; out = log(w/(w0+w1))
// Only class-0 of xt (one-hot) and x0 (K=2 log_softmax) are read.

__global__ void __launch_bounds__(256, 8) qpost_kernel(const float* __restrict__ xt,
                                                       const float* __restrict__ x0,
                                                       float* __restrict__ out,
                                                       const int* __restrict__ t_raw,
                                                       const float* __restrict__ la,
                                                       const float* __restrict__ l1a,
                                                       const float* __restrict__ lab,
                                                       const float* __restrict__ l1ab) {
    unsigned tid = blockIdx.x * 256u + threadIdx.x;
    size_t e = (size_t)tid << 3;                   // 8 spatial elems per thread
    unsigned b = (unsigned)(e >> 20);              // batch (uniform per block)
    size_t base = ((size_t)b << 21) + (e & (((size_t)1 << 20) - 1));
    const size_t cstr = (size_t)1 << 20;           // class stride

    // ---- front-batched streaming loads FIRST (MLP=4, R6-proven) ----
    float4 xtA = __ldcs((const float4*)(xt + base));
    float4 xtB = __ldcs((const float4*)(xt + base + 4));
    float4 x0A = __ldcs((const float4*)(x0 + base));
    float4 x0B = __ldcs((const float4*)(x0 + base + 4));

    // ---- lane-0 params (scalar L1-hit loads), overlapped with load stall ----
    float Qh = 0.f, Ql = 0.f, ab = 0.f, c = 0.f;
    if ((threadIdx.x & 31) == 0) {
        // int64-vs-int32 sniff (t in [0,1000); int64 LE high words are 0)
        int hw = t_raw[1] | t_raw[3] | t_raw[5] | t_raw[7];
        int t = (hw == 0) ? t_raw[2 * b] : t_raw[b];
        float alpha = __expf(la[t]);
        float oma   = __expf(l1a[t]);              // 1 - alpha (+1e-40)
        Qh = fmaf(0.5f, oma, alpha);
        Ql = fmaf(0.5f, oma, 1e-30f * alpha);
        if (t == 0) { ab = 1.0f; c = 0.0f; }       // exact t==0 unification
        else        { ab = __expf(lab[t - 1]); c = 0.5f * __expf(l1ab[t - 1]); }
    }
    Qh = __shfl_sync(0xFFFFFFFFu, Qh, 0);
    Ql = __shfl_sync(0xFFFFFFFFu, Ql, 0);
    ab = __shfl_sync(0xFFFFFFFFu, ab, 0);
    c  = __shfl_sync(0xFFFFFFFFu, c,  0);
    float abc = ab + c;

    // ---- compute + store per quad (short live ranges, regs <= 32) ----
    #pragma unroll
    for (int h = 0; h < 2; h++) {
        float4 xq = h ? xtB : xtA;
        float4 pq = h ? x0B : x0A;
        float4 o0, o1;
        #pragma unroll
        for (int k = 0; k < 4; k++) {
            float e0 = __expf(((const float*)&pq)[k]);   // exp(x01) = 1-e0 (K=2)
            float f0 = fmaf(ab, e0, c);
            float f1 = fmaf(-ab, e0, abc);               // ab*(1-e0)+c
            bool hi = (((const float*)&xq)[k] > -1.0f);  // one-hot hit on class 0?
            float w0 = f0 * (hi ? Qh : Ql);
            float w1 = f1 * (hi ? Ql : Qh);
            float r = __fdividef(1.0f, w0 + w1);
            ((float*)&o0)[k] = __logf(w0 * r);
            ((float*)&o1)[k] = __logf(w1 * r);
        }
        __stcs((float4*)(out + base + 4 * h),        o0);
        __stcs((float4*)(out + base + cstr + 4 * h), o1);
    }
}

extern "C" void kernel_launch(void* const* d_in, const int* in_sizes, int n_in,
                              void* d_out, int out_size) {
    const float* log_x_t = (const float*)d_in[0];
    const float* log_x_0 = (const float*)d_in[1];
    const float* la      = (const float*)d_in[2];
    const float* l1a     = (const float*)d_in[3];
    const float* lab     = (const float*)d_in[4];
    const float* l1ab    = (const float*)d_in[5];
    const int*   t_raw   = (const int*)d_in[6];

    // 16 * 2^20 spatial / 8 per thread = 2,097,152 threads = 8192 blocks
    qpost_kernel<<<8192, 256>>>(log_x_t, log_x_0, (float*)d_out,
                                t_raw, la, l1a, lab, l1ab);
}